// round 16
// baseline (speedup 1.0000x reference)
#include <cuda_runtime.h>
#include <cuda_bf16.h>
#include <cstdint>

// ---------------------------------------------------------------------------
// Spk_Attention: B=512, N=256, H=512. sm_103 plain target -> mma.sync bf16
// m16n8k16 3xBF16.  R16: R15 (best) + softmax split 4-way over h quarters
// (128-thread CTAs, better wave packing). All other kernels byte-identical.
// ---------------------------------------------------------------------------

#define Bsz 512
#define Nn  256
#define Hh  512
#define HB  (Hh * Hh)          // 262144

__device__ float g_scores_part[4 * Bsz * Nn];
__device__ float g_resps[Bsz * Hh];
__device__ float g_dual_part[8 * HB];   // [z(2)][kc(4)][512*512]
__device__ float g_fin_part[8 * HB];    // [kc(8)][512*512]
__device__ __nv_bfloat16 g_Bhi[HB];     // WsT hi plane [n][k]
__device__ __nv_bfloat16 g_Blo[HB];

// ---------------- helpers --------------------------------------------------
__device__ __forceinline__ float tanh_fast(float x) {
    float y;
    asm("tanh.approx.f32 %0, %1;" : "=f"(y) : "f"(x));
    return y;
}
__device__ __forceinline__ uint32_t smem_u32(const void* p) {
    uint32_t a;
    asm("{ .reg .u64 t; cvta.to.shared.u64 t, %1; cvt.u32.u64 %0, t; }"
        : "=r"(a) : "l"(p));
    return a;
}
__device__ __forceinline__ void cp16(uint32_t dst, const void* src) {
    asm volatile("cp.async.cg.shared.global [%0], [%1], 16;"
                 :: "r"(dst), "l"(src) : "memory");
}
__device__ __forceinline__ void ldsm4(uint32_t* r, uint32_t addr) {
    asm volatile("ldmatrix.sync.aligned.m8n8.x4.shared.b16 {%0,%1,%2,%3}, [%4];"
                 : "=r"(r[0]), "=r"(r[1]), "=r"(r[2]), "=r"(r[3]) : "r"(addr));
}
__device__ __forceinline__ void mma_bf16(float* d, const uint32_t* a,
                                         uint32_t b0, uint32_t b1) {
    asm volatile(
        "mma.sync.aligned.m16n8k16.row.col.f32.bf16.bf16.f32 "
        "{%0,%1,%2,%3}, {%4,%5,%6,%7}, {%8,%9}, {%0,%1,%2,%3};"
        : "+f"(d[0]), "+f"(d[1]), "+f"(d[2]), "+f"(d[3])
        : "r"(a[0]), "r"(a[1]), "r"(a[2]), "r"(a[3]), "r"(b0), "r"(b1));
}
__device__ __forceinline__ void split1(float v, __nv_bfloat16& h,
                                       __nv_bfloat16& l) {
    h = __float2bfloat16(v);
    l = __float2bfloat16(v - __bfloat162float(h));
}
// B-plane swizzle (64B rows, 4 chunks)
__device__ __forceinline__ uint32_t swz(uint32_t r, uint32_t c) {
    return r * 64u + ((c ^ ((r >> 1) & 3u)) << 4);
}
// A fp32 tile swizzle (128B rows, 8 chunks)
__device__ __forceinline__ uint32_t swzA(uint32_t r, uint32_t c) {
    return r * 128u + ((c ^ (r & 7u)) << 4);
}
__device__ __forceinline__ float2 lds64(uint32_t addr) {
    float2 v;
    asm volatile("ld.shared.v2.f32 {%0,%1}, [%2];"
                 : "=f"(v.x), "=f"(v.y) : "r"(addr));
    return v;
}
// fp32 pair -> (hi bf16x2, lo bf16x2)
__device__ __forceinline__ void cvt_pair(float2 p, uint32_t& hi, uint32_t& lo) {
    asm("cvt.rn.bf16x2.f32 %0, %1, %2;" : "=r"(hi) : "f"(p.y), "f"(p.x));
    const float hx = __uint_as_float(hi << 16);
    const float hy = __uint_as_float(hi & 0xffff0000u);
    const float lx = p.x - hx;
    const float ly = p.y - hy;
    asm("cvt.rn.bf16x2.f32 %0, %1, %2;" : "=r"(lo) : "f"(ly), "f"(lx));
}

// ---------------------------------------------------------------------------
// Small GEMM split-K body: 64 rows x 64 cols per CTA over KTILES k16 tiles,
// 256 threads (16x16), microtile 4x4, LDS.128 loads.
// ---------------------------------------------------------------------------
template <bool TRANSB, int KTILES>
__device__ __forceinline__
void gemm_k(const float* __restrict__ A,
            const float* __restrict__ B,
            float* __restrict__ outp,
            int row0, int col0, int kbeg)
{
    __shared__ float As[16][68];   // [k][row]
    __shared__ float Bs[16][68];   // [k][col]
    const int tid = threadIdx.x;
    const int tx = tid & 15, ty = tid >> 4;

    float acc[4][4];
    #pragma unroll
    for (int i = 0; i < 4; i++)
        #pragma unroll
        for (int j = 0; j < 4; j++) acc[i][j] = 0.0f;

    #pragma unroll
    for (int kt = 0; kt < KTILES; kt++) {
        const int k0 = kbeg + kt * 16;
        {   // A: 64 rows x 16 k, one float4 per thread, transposed store
            const int r = tid >> 2, k4 = (tid & 3) * 4;
            const float4 v = *(const float4*)&A[(size_t)(row0 + r) * Hh + k0 + k4];
            As[k4 + 0][r] = v.x; As[k4 + 1][r] = v.y;
            As[k4 + 2][r] = v.z; As[k4 + 3][r] = v.w;
        }
        if (TRANSB) {
            const int c = tid >> 2, k4 = (tid & 3) * 4;
            const float4 v = *(const float4*)&B[(size_t)(col0 + c) * Hh + k0 + k4];
            Bs[k4 + 0][c] = v.x; Bs[k4 + 1][c] = v.y;
            Bs[k4 + 2][c] = v.z; Bs[k4 + 3][c] = v.w;
        } else {
            const int k = tid >> 4, c4 = (tid & 15) * 4;
            *(float4*)&Bs[k][c4] = *(const float4*)&B[(size_t)(k0 + k) * Hh + col0 + c4];
        }
        __syncthreads();

        #pragma unroll
        for (int k = 0; k < 16; k++) {
            const float4 a = *(const float4*)&As[k][ty * 4];
            const float4 bb = *(const float4*)&Bs[k][tx * 4];
            const float av[4] = {a.x, a.y, a.z, a.w};
            const float bv[4] = {bb.x, bb.y, bb.z, bb.w};
            #pragma unroll
            for (int i = 0; i < 4; i++)
                #pragma unroll
                for (int j = 0; j < 4; j++)
                    acc[i][j] = fmaf(av[i], bv[j], acc[i][j]);
        }
        __syncthreads();
    }

    #pragma unroll
    for (int i = 0; i < 4; i++)
        #pragma unroll
        for (int j = 0; j < 4; j++)
            outp[(size_t)(row0 + ty * 4 + i) * Hh + col0 + tx * 4 + j] = acc[i][j];
}

// ---------------------------------------------------------------------------
// Fused prep: blockIdx.x partition (R13/R15 config)
//   [0,512):   dual GEMM split-K4 64x64: z = bx>>8, kc = (bx>>6)&3, rem = bx&63
//   [512,640): split_ws (Ws -> Bhi/Blo planes)
// ---------------------------------------------------------------------------
__global__ __launch_bounds__(256)
void prep_fused(const float* __restrict__ Ws,
                const float* __restrict__ tr,
                const float* __restrict__ Wr,
                const float* __restrict__ Wx,
                __nv_bfloat16* __restrict__ Bhi,
                __nv_bfloat16* __restrict__ Blo,
                float* __restrict__ dual_part)
{
    const int bx = blockIdx.x;
    if (bx < 512) {
        const int z = bx >> 8, kc = (bx >> 6) & 3, rem = bx & 63;
        const int col0 = (rem & 7) * 64, row0 = (rem >> 3) * 64;
        float* outp = dual_part + (size_t)(z * 4 + kc) * HB;
        if (z == 0)
            gemm_k<false, 8>(tr, Wr, outp, row0, col0, kc * 128);
        else
            gemm_k<true, 8>(tr, Wx, outp, row0, col0, kc * 128);
    } else {
        const int base = (bx - 512) * 1024 + threadIdx.x * 4;
        #pragma unroll
        for (int i = 0; i < 4; i++) {
            const int j = base + i;
            const int n = j >> 8, p = j & 255;
            __nv_bfloat162 h2, l2;
            split1(Ws[(2 * p) * Hh + n],     h2.x, l2.x);
            split1(Ws[(2 * p + 1) * Hh + n], h2.y, l2.y);
            ((__nv_bfloat162*)Bhi)[(size_t)n * (Hh / 2) + p] = h2;
            ((__nv_bfloat162*)Blo)[(size_t)n * (Hh / 2) + p] = l2;
        }
    }
}

// ---------------------------------------------------------------------------
// score kernel (byte-identical logic to R11-R15; WR sums 4 split-K partials)
// ---------------------------------------------------------------------------
#define A_W     4096u
#define PLANE_W 2048u
#define STG_W   (A_W + 2u * PLANE_W)
#define NSTG    3
#define SM_W    (NSTG * STG_W + 512)
#define SM_BYTES (SM_W * 4)

__global__ __launch_bounds__(256, 2)
void score_mma(const float* __restrict__ Afp,
               const __nv_bfloat16* __restrict__ Bhi,
               const __nv_bfloat16* __restrict__ Blo,
               const float* __restrict__ dual_part,
               const float* __restrict__ wvec,
               float* __restrict__ scores_part)
{
    extern __shared__ uint32_t smw[];
    float* WRs = (float*)(smw + NSTG * STG_W);
    float* WVs = WRs + 128;
    float* sp2 = WVs + 128;

    const int tid  = threadIdx.x;
    const int lane = tid & 31, wid = tid >> 5;
    const int wm = wid & 3, wn = wid >> 2;
    const int g  = lane >> 2, tg = lane & 3;
    const int col0 = blockIdx.x * 128;
    const int row0 = blockIdx.y * 128;
    const int b    = row0 >> 8;

    if (tid < 128) {
        const size_t o = (size_t)b * Hh + col0 + tid;
        WRs[tid] = ((dual_part[o] + dual_part[HB + o])
                  + (dual_part[2 * (size_t)HB + o] + dual_part[3 * (size_t)HB + o]));
        WVs[tid] = wvec[col0 + tid];
    }

    const uint32_t sbase = smem_u32(smw);

    const uint32_t b_row = (lane & 7) | (((lane >> 4) & 1) << 3);
    const uint32_t b_chk = (lane >> 3) & 1;
    const uint32_t wsel = ((2u * tg) & 3u) * 4u;
    const uint32_t cbase = (uint32_t)(tg >> 1);

    auto load_stage = [&](int kk, int slot) {
        const uint32_t db = sbase + (uint32_t)slot * (STG_W * 4);
        #pragma unroll
        for (int i = 0; i < 8; i++) {
            const int idx = tid + 256 * i;
            if (i < 4) {
                const uint32_t r = (uint32_t)(idx >> 3), c = (uint32_t)(idx & 7);
                cp16(db + swzA(r, c),
                     Afp + (size_t)(row0 + r) * Hh + kk * 32 + c * 4);
            } else {
                const int j = idx - 1024;
                const int plane = j >> 9;
                const uint32_t r = (uint32_t)((j >> 2) & 127), c = (uint32_t)(j & 3);
                const __nv_bfloat16* src = (plane == 0 ? Bhi : Blo)
                                           + (size_t)(col0 + r) * Hh + kk * 32 + c * 8;
                cp16(db + (A_W + plane * PLANE_W) * 4u + swz(r, c), src);
            }
        }
        asm volatile("cp.async.commit_group;" ::: "memory");
    };

    load_stage(0, 0);
    load_stage(1, 1);

    float acc[2][8][4];
    #pragma unroll
    for (int mt = 0; mt < 2; mt++)
        #pragma unroll
        for (int nt = 0; nt < 8; nt++)
            #pragma unroll
            for (int c = 0; c < 4; c++) acc[mt][nt][c] = 0.0f;

    #pragma unroll 1
    for (int kk = 0; kk < 16; kk++) {
        if (kk < 15) asm volatile("cp.async.wait_group 1;" ::: "memory");
        else         asm volatile("cp.async.wait_group 0;" ::: "memory");
        __syncthreads();

        if (kk + 2 < 16) load_stage(kk + 2, (kk + 2) % 3);

        const uint32_t stg  = sbase + (uint32_t)(kk % 3) * (STG_W * 4);
        const uint32_t pA   = stg;
        const uint32_t pBhi = stg + A_W * 4;
        const uint32_t pBlo = stg + (A_W + PLANE_W) * 4;

        #pragma unroll
        for (int ks = 0; ks < 2; ks++) {
            uint32_t ahi[2][4], alo[2][4];
            const uint32_t c0 = 4u * ks + cbase;
            const uint32_t c1 = c0 + 2u;
            #pragma unroll
            for (int mt = 0; mt < 2; mt++) {
                const uint32_t rb = (uint32_t)(wm * 32 + mt * 16);
                const uint32_t r0 = rb + g, r1 = rb + 8 + g;
                const uint32_t x0 = pA + r0 * 128u + ((c0 ^ g) << 4) + wsel;
                const uint32_t x1 = pA + r1 * 128u + ((c0 ^ g) << 4) + wsel;
                const uint32_t x2 = pA + r0 * 128u + ((c1 ^ g) << 4) + wsel;
                const uint32_t x3 = pA + r1 * 128u + ((c1 ^ g) << 4) + wsel;
                cvt_pair(lds64(x0), ahi[mt][0], alo[mt][0]);
                cvt_pair(lds64(x1), ahi[mt][1], alo[mt][1]);
                cvt_pair(lds64(x2), ahi[mt][2], alo[mt][2]);
                cvt_pair(lds64(x3), ahi[mt][3], alo[mt][3]);
            }
            #pragma unroll
            for (int ntp = 0; ntp < 4; ntp++) {
                const uint32_t r = wn * 64 + ntp * 16 + b_row;
                const uint32_t off = swz(r, ks * 2 + b_chk);
                uint32_t bh[4], bl[4];
                ldsm4(bh, pBhi + off);
                ldsm4(bl, pBlo + off);
                #pragma unroll
                for (int half = 0; half < 2; half++) {
                    const int nt = ntp * 2 + half;
                    const uint32_t b0h = bh[half * 2], b1h = bh[half * 2 + 1];
                    const uint32_t b0l = bl[half * 2], b1l = bl[half * 2 + 1];
                    #pragma unroll
                    for (int mt = 0; mt < 2; mt++) {
                        mma_bf16(acc[mt][nt], ahi[mt], b0l, b1l);
                        mma_bf16(acc[mt][nt], alo[mt], b0h, b1h);
                        mma_bf16(acc[mt][nt], ahi[mt], b0h, b1h);
                    }
                }
            }
        }
    }

    #pragma unroll
    for (int mt = 0; mt < 2; mt++) {
        float plo = 0.0f, phi = 0.0f;
        #pragma unroll
        for (int nt = 0; nt < 8; nt++) {
            const int c0 = wn * 64 + nt * 8 + 2 * tg;
            const int c1 = c0 + 1;
            plo += tanh_fast(acc[mt][nt][0] + WRs[c0]) * WVs[c0]
                 + tanh_fast(acc[mt][nt][1] + WRs[c1]) * WVs[c1];
            phi += tanh_fast(acc[mt][nt][2] + WRs[c0]) * WVs[c0]
                 + tanh_fast(acc[mt][nt][3] + WRs[c1]) * WVs[c1];
        }
        plo += __shfl_xor_sync(0xFFFFFFFFu, plo, 1);
        plo += __shfl_xor_sync(0xFFFFFFFFu, plo, 2);
        phi += __shfl_xor_sync(0xFFFFFFFFu, phi, 1);
        phi += __shfl_xor_sync(0xFFFFFFFFu, phi, 2);
        if (tg == 0) {
            sp2[wn * 128 + wm * 32 + mt * 16 + g]     = plo;
            sp2[wn * 128 + wm * 32 + mt * 16 + 8 + g] = phi;
        }
    }
    __syncthreads();
    if (tid < 128)
        scores_part[(size_t)blockIdx.x * (Bsz * Nn) + row0 + tid] =
            sp2[tid] + sp2[128 + tid];
}

// ---------------------------------------------------------------------------
// Per-batch softmax + resp_s, split 4-way over h quarters: grid (512 b, 4 q),
// 128 threads. Each block recomputes the 256-wide softmax (threads own 2 n),
// quarter 0 writes alpha. Reduction tree identical to the 256-slot version.
// ---------------------------------------------------------------------------
__global__ __launch_bounds__(128)
void softmax_weight_kernel(const float* __restrict__ scores_part,
                           const float* __restrict__ mask,
                           const float* __restrict__ emb,
                           float* __restrict__ alpha_out,
                           float* __restrict__ resps)
{
    const int b = blockIdx.x;
    const int quarter = blockIdx.y;
    const int tid = threadIdx.x;     // 0..127
    __shared__ float sa[256];
    __shared__ float red[256];

    // each thread computes t for n = tid and n = tid + 128
    #pragma unroll
    for (int half = 0; half < 2; half++) {
        const int n = tid + half * 128;
        const size_t i = (size_t)b * Nn + n;
        float s = scores_part[i];
        s += scores_part[(size_t)(Bsz * Nn) + i];
        s += scores_part[(size_t)(2 * Bsz * Nn) + i];
        s += scores_part[(size_t)(3 * Bsz * Nn) + i];
        red[n] = s * mask[i];
        sa[n]  = red[n];   // stash t for exp later
    }
    __syncthreads();
    // max over 256 slots (identical tree to 256-thread version)
    #pragma unroll
    for (int st = 128; st > 0; st >>= 1) {
        if (tid < st) red[tid] = fmaxf(red[tid], red[tid + st]);
        __syncthreads();
    }
    const float m = red[0];
    __syncthreads();

    #pragma unroll
    for (int half = 0; half < 2; half++) {
        const int n = tid + half * 128;
        red[n] = __expf(sa[n] - m);
    }
    __syncthreads();
    // stash exps before the sum tree destroys red[0:128]
    float e0 = red[tid], e1 = red[tid + 128];
    #pragma unroll
    for (int st = 128; st > 0; st >>= 1) {
        if (tid < st) red[tid] += red[tid + st];
        __syncthreads();
    }
    const float inv = 1.0f / red[0];
    __syncthreads();

    sa[tid]       = e0 * inv;
    sa[tid + 128] = e1 * inv;
    if (quarter == 0) {
        alpha_out[(size_t)b * Nn + tid]       = sa[tid];
        alpha_out[(size_t)b * Nn + tid + 128] = sa[tid + 128];
    }
    __syncthreads();

    const int h = quarter * 128 + tid;
    const float* eb = emb + (size_t)b * Nn * Hh + h;
    float c0 = 0.f, c1 = 0.f, c2 = 0.f, c3 = 0.f;
    float c4 = 0.f, c5 = 0.f, c6 = 0.f, c7 = 0.f;
    #pragma unroll 1
    for (int n = 0; n < Nn; n += 8) {
        c0 = fmaf(sa[n    ], eb[(size_t)(n    ) * Hh], c0);
        c1 = fmaf(sa[n + 1], eb[(size_t)(n + 1) * Hh], c1);
        c2 = fmaf(sa[n + 2], eb[(size_t)(n + 2) * Hh], c2);
        c3 = fmaf(sa[n + 3], eb[(size_t)(n + 3) * Hh], c3);
        c4 = fmaf(sa[n + 4], eb[(size_t)(n + 4) * Hh], c4);
        c5 = fmaf(sa[n + 5], eb[(size_t)(n + 5) * Hh], c5);
        c6 = fmaf(sa[n + 6], eb[(size_t)(n + 6) * Hh], c6);
        c7 = fmaf(sa[n + 7], eb[(size_t)(n + 7) * Hh], c7);
    }
    resps[b * Hh + h] = ((c0 + c1) + (c2 + c3)) + ((c4 + c5) + (c6 + c7));
}

// ---------------------------------------------------------------------------
// Final GEMM split-K8: partial = presps @ Wp^T over 64-wide K chunk
// grid (8 col, 8 row, 8 kc); 64x64 tiles, 4-tile chain.
// ---------------------------------------------------------------------------
__global__ __launch_bounds__(256)
void gemm_final_k(const float* __restrict__ A,
                  const float* __restrict__ B,
                  float* __restrict__ fin_part)
{
    const int kc = blockIdx.z;
    gemm_k<true, 4>(A, B, fin_part + (size_t)kc * HB,
                    blockIdx.y * 64, blockIdx.x * 64, kc * 64);
}

// combine: out = tanh(sum 8 fin partials + sum 4 rx partials)  (deterministic)
__global__ __launch_bounds__(512)
void combine_final(const float* __restrict__ fin_part,
                   const float* __restrict__ dual_part,
                   float* __restrict__ out)
{
    const size_t idx = (size_t)blockIdx.x * 512 + threadIdx.x;
    float f = ((fin_part[idx] + fin_part[HB + idx])
             + (fin_part[2 * (size_t)HB + idx] + fin_part[3 * (size_t)HB + idx]));
    f += ((fin_part[4 * (size_t)HB + idx] + fin_part[5 * (size_t)HB + idx])
        + (fin_part[6 * (size_t)HB + idx] + fin_part[7 * (size_t)HB + idx]));
    const float* rx = dual_part + 4 * (size_t)HB;
    float r = ((rx[idx] + rx[HB + idx])
             + (rx[2 * (size_t)HB + idx] + rx[3 * (size_t)HB + idx]));
    out[idx] = tanhf(f + r);
}

// ---------------------------------------------------------------------------
extern "C" void kernel_launch(void* const* d_in, const int* in_sizes, int n_in,
                              void* d_out, int out_size)
{
    const float* spk  = (const float*)d_in[0];
    const float* mask = (const float*)d_in[1];
    const float* tr   = (const float*)d_in[2];
    const float* Ws   = (const float*)d_in[3];
    const float* Wr   = (const float*)d_in[4];
    const float* w    = (const float*)d_in[5];
    const float* Wp   = (const float*)d_in[6];
    const float* Wx   = (const float*)d_in[7];

    float* out = (float*)d_out;
    float* resp_out  = out;
    float* alpha_out = out + Bsz * Hh;

    float *pspart, *presps, *pdual, *pfin;
    __nv_bfloat16 *pBhi, *pBlo;
    cudaGetSymbolAddress((void**)&pspart, g_scores_part);
    cudaGetSymbolAddress((void**)&presps, g_resps);
    cudaGetSymbolAddress((void**)&pdual, g_dual_part);
    cudaGetSymbolAddress((void**)&pfin, g_fin_part);
    cudaGetSymbolAddress((void**)&pBhi, g_Bhi);
    cudaGetSymbolAddress((void**)&pBlo, g_Blo);

    static bool attr_set = false;
    if (!attr_set) {
        cudaFuncSetAttribute(score_mma,
                             cudaFuncAttributeMaxDynamicSharedMemorySize,
                             SM_BYTES);
        attr_set = true;
    }

    prep_fused<<<640, 256>>>(Ws, tr, Wr, Wx, pBhi, pBlo, pdual);
    score_mma<<<dim3(4, 1024), 256, SM_BYTES>>>(spk, pBhi, pBlo,
                                                pdual, w, pspart);
    softmax_weight_kernel<<<dim3(512, 4), 128>>>(pspart, mask, spk,
                                                 alpha_out, presps);
    gemm_final_k<<<dim3(8, 8, 8), 256>>>(presps, Wp, pfin);
    combine_final<<<512, 512>>>(pfin, pdual, resp_out);
}

// round 17
// speedup vs baseline: 1.0032x; 1.0032x over previous
#include <cuda_runtime.h>
#include <cuda_bf16.h>
#include <cstdint>

// ---------------------------------------------------------------------------
// Spk_Attention: B=512, N=256, H=512. sm_103 plain target -> mma.sync bf16
// m16n8k16 3xBF16.  R17 == R15 (best measured): score/softmax = R13,
// dual-prep = split-K4, final GEMM = split-K8 lean tiles.
// ---------------------------------------------------------------------------

#define Bsz 512
#define Nn  256
#define Hh  512
#define HB  (Hh * Hh)          // 262144

__device__ float g_scores_part[4 * Bsz * Nn];
__device__ float g_resps[Bsz * Hh];
__device__ float g_dual_part[8 * HB];   // [z(2)][kc(4)][512*512]
__device__ float g_fin_part[8 * HB];    // [kc(8)][512*512]
__device__ __nv_bfloat16 g_Bhi[HB];     // WsT hi plane [n][k]
__device__ __nv_bfloat16 g_Blo[HB];

// ---------------- helpers --------------------------------------------------
__device__ __forceinline__ float tanh_fast(float x) {
    float y;
    asm("tanh.approx.f32 %0, %1;" : "=f"(y) : "f"(x));
    return y;
}
__device__ __forceinline__ uint32_t smem_u32(const void* p) {
    uint32_t a;
    asm("{ .reg .u64 t; cvta.to.shared.u64 t, %1; cvt.u32.u64 %0, t; }"
        : "=r"(a) : "l"(p));
    return a;
}
__device__ __forceinline__ void cp16(uint32_t dst, const void* src) {
    asm volatile("cp.async.cg.shared.global [%0], [%1], 16;"
                 :: "r"(dst), "l"(src) : "memory");
}
__device__ __forceinline__ void ldsm4(uint32_t* r, uint32_t addr) {
    asm volatile("ldmatrix.sync.aligned.m8n8.x4.shared.b16 {%0,%1,%2,%3}, [%4];"
                 : "=r"(r[0]), "=r"(r[1]), "=r"(r[2]), "=r"(r[3]) : "r"(addr));
}
__device__ __forceinline__ void mma_bf16(float* d, const uint32_t* a,
                                         uint32_t b0, uint32_t b1) {
    asm volatile(
        "mma.sync.aligned.m16n8k16.row.col.f32.bf16.bf16.f32 "
        "{%0,%1,%2,%3}, {%4,%5,%6,%7}, {%8,%9}, {%0,%1,%2,%3};"
        : "+f"(d[0]), "+f"(d[1]), "+f"(d[2]), "+f"(d[3])
        : "r"(a[0]), "r"(a[1]), "r"(a[2]), "r"(a[3]), "r"(b0), "r"(b1));
}
__device__ __forceinline__ void split1(float v, __nv_bfloat16& h,
                                       __nv_bfloat16& l) {
    h = __float2bfloat16(v);
    l = __float2bfloat16(v - __bfloat162float(h));
}
// B-plane swizzle (64B rows, 4 chunks)
__device__ __forceinline__ uint32_t swz(uint32_t r, uint32_t c) {
    return r * 64u + ((c ^ ((r >> 1) & 3u)) << 4);
}
// A fp32 tile swizzle (128B rows, 8 chunks)
__device__ __forceinline__ uint32_t swzA(uint32_t r, uint32_t c) {
    return r * 128u + ((c ^ (r & 7u)) << 4);
}
__device__ __forceinline__ float2 lds64(uint32_t addr) {
    float2 v;
    asm volatile("ld.shared.v2.f32 {%0,%1}, [%2];"
                 : "=f"(v.x), "=f"(v.y) : "r"(addr));
    return v;
}
// fp32 pair -> (hi bf16x2, lo bf16x2)
__device__ __forceinline__ void cvt_pair(float2 p, uint32_t& hi, uint32_t& lo) {
    asm("cvt.rn.bf16x2.f32 %0, %1, %2;" : "=r"(hi) : "f"(p.y), "f"(p.x));
    const float hx = __uint_as_float(hi << 16);
    const float hy = __uint_as_float(hi & 0xffff0000u);
    const float lx = p.x - hx;
    const float ly = p.y - hy;
    asm("cvt.rn.bf16x2.f32 %0, %1, %2;" : "=r"(lo) : "f"(ly), "f"(lx));
}

// ---------------------------------------------------------------------------
// Small GEMM split-K body: 64 rows x 64 cols per CTA over KTILES k16 tiles,
// 256 threads (16x16), microtile 4x4, LDS.128 loads.
// ---------------------------------------------------------------------------
template <bool TRANSB, int KTILES>
__device__ __forceinline__
void gemm_k(const float* __restrict__ A,
            const float* __restrict__ B,
            float* __restrict__ outp,
            int row0, int col0, int kbeg)
{
    __shared__ float As[16][68];   // [k][row]
    __shared__ float Bs[16][68];   // [k][col]
    const int tid = threadIdx.x;
    const int tx = tid & 15, ty = tid >> 4;

    float acc[4][4];
    #pragma unroll
    for (int i = 0; i < 4; i++)
        #pragma unroll
        for (int j = 0; j < 4; j++) acc[i][j] = 0.0f;

    #pragma unroll
    for (int kt = 0; kt < KTILES; kt++) {
        const int k0 = kbeg + kt * 16;
        {   // A: 64 rows x 16 k, one float4 per thread, transposed store
            const int r = tid >> 2, k4 = (tid & 3) * 4;
            const float4 v = *(const float4*)&A[(size_t)(row0 + r) * Hh + k0 + k4];
            As[k4 + 0][r] = v.x; As[k4 + 1][r] = v.y;
            As[k4 + 2][r] = v.z; As[k4 + 3][r] = v.w;
        }
        if (TRANSB) {
            const int c = tid >> 2, k4 = (tid & 3) * 4;
            const float4 v = *(const float4*)&B[(size_t)(col0 + c) * Hh + k0 + k4];
            Bs[k4 + 0][c] = v.x; Bs[k4 + 1][c] = v.y;
            Bs[k4 + 2][c] = v.z; Bs[k4 + 3][c] = v.w;
        } else {
            const int k = tid >> 4, c4 = (tid & 15) * 4;
            *(float4*)&Bs[k][c4] = *(const float4*)&B[(size_t)(k0 + k) * Hh + col0 + c4];
        }
        __syncthreads();

        #pragma unroll
        for (int k = 0; k < 16; k++) {
            const float4 a = *(const float4*)&As[k][ty * 4];
            const float4 bb = *(const float4*)&Bs[k][tx * 4];
            const float av[4] = {a.x, a.y, a.z, a.w};
            const float bv[4] = {bb.x, bb.y, bb.z, bb.w};
            #pragma unroll
            for (int i = 0; i < 4; i++)
                #pragma unroll
                for (int j = 0; j < 4; j++)
                    acc[i][j] = fmaf(av[i], bv[j], acc[i][j]);
        }
        __syncthreads();
    }

    #pragma unroll
    for (int i = 0; i < 4; i++)
        #pragma unroll
        for (int j = 0; j < 4; j++)
            outp[(size_t)(row0 + ty * 4 + i) * Hh + col0 + tx * 4 + j] = acc[i][j];
}

// ---------------------------------------------------------------------------
// Fused prep: blockIdx.x partition
//   [0,512):   dual GEMM split-K4 64x64: z = bx>>8, kc = (bx>>6)&3, rem = bx&63
//   [512,640): split_ws (Ws -> Bhi/Blo planes)
// ---------------------------------------------------------------------------
__global__ __launch_bounds__(256)
void prep_fused(const float* __restrict__ Ws,
                const float* __restrict__ tr,
                const float* __restrict__ Wr,
                const float* __restrict__ Wx,
                __nv_bfloat16* __restrict__ Bhi,
                __nv_bfloat16* __restrict__ Blo,
                float* __restrict__ dual_part)
{
    const int bx = blockIdx.x;
    if (bx < 512) {
        const int z = bx >> 8, kc = (bx >> 6) & 3, rem = bx & 63;
        const int col0 = (rem & 7) * 64, row0 = (rem >> 3) * 64;
        float* outp = dual_part + (size_t)(z * 4 + kc) * HB;
        if (z == 0)
            gemm_k<false, 8>(tr, Wr, outp, row0, col0, kc * 128);
        else
            gemm_k<true, 8>(tr, Wx, outp, row0, col0, kc * 128);
    } else {
        const int base = (bx - 512) * 1024 + threadIdx.x * 4;
        #pragma unroll
        for (int i = 0; i < 4; i++) {
            const int j = base + i;
            const int n = j >> 8, p = j & 255;
            __nv_bfloat162 h2, l2;
            split1(Ws[(2 * p) * Hh + n],     h2.x, l2.x);
            split1(Ws[(2 * p + 1) * Hh + n], h2.y, l2.y);
            ((__nv_bfloat162*)Bhi)[(size_t)n * (Hh / 2) + p] = h2;
            ((__nv_bfloat162*)Blo)[(size_t)n * (Hh / 2) + p] = l2;
        }
    }
}

// ---------------------------------------------------------------------------
// score kernel (byte-identical logic to R11-R15; WR sums 4 split-K partials)
// ---------------------------------------------------------------------------
#define A_W     4096u
#define PLANE_W 2048u
#define STG_W   (A_W + 2u * PLANE_W)
#define NSTG    3
#define SM_W    (NSTG * STG_W + 512)
#define SM_BYTES (SM_W * 4)

__global__ __launch_bounds__(256, 2)
void score_mma(const float* __restrict__ Afp,
               const __nv_bfloat16* __restrict__ Bhi,
               const __nv_bfloat16* __restrict__ Blo,
               const float* __restrict__ dual_part,
               const float* __restrict__ wvec,
               float* __restrict__ scores_part)
{
    extern __shared__ uint32_t smw[];
    float* WRs = (float*)(smw + NSTG * STG_W);
    float* WVs = WRs + 128;
    float* sp2 = WVs + 128;

    const int tid  = threadIdx.x;
    const int lane = tid & 31, wid = tid >> 5;
    const int wm = wid & 3, wn = wid >> 2;
    const int g  = lane >> 2, tg = lane & 3;
    const int col0 = blockIdx.x * 128;
    const int row0 = blockIdx.y * 128;
    const int b    = row0 >> 8;

    if (tid < 128) {
        const size_t o = (size_t)b * Hh + col0 + tid;
        WRs[tid] = ((dual_part[o] + dual_part[HB + o])
                  + (dual_part[2 * (size_t)HB + o] + dual_part[3 * (size_t)HB + o]));
        WVs[tid] = wvec[col0 + tid];
    }

    const uint32_t sbase = smem_u32(smw);

    const uint32_t b_row = (lane & 7) | (((lane >> 4) & 1) << 3);
    const uint32_t b_chk = (lane >> 3) & 1;
    const uint32_t wsel = ((2u * tg) & 3u) * 4u;
    const uint32_t cbase = (uint32_t)(tg >> 1);

    auto load_stage = [&](int kk, int slot) {
        const uint32_t db = sbase + (uint32_t)slot * (STG_W * 4);
        #pragma unroll
        for (int i = 0; i < 8; i++) {
            const int idx = tid + 256 * i;
            if (i < 4) {
                const uint32_t r = (uint32_t)(idx >> 3), c = (uint32_t)(idx & 7);
                cp16(db + swzA(r, c),
                     Afp + (size_t)(row0 + r) * Hh + kk * 32 + c * 4);
            } else {
                const int j = idx - 1024;
                const int plane = j >> 9;
                const uint32_t r = (uint32_t)((j >> 2) & 127), c = (uint32_t)(j & 3);
                const __nv_bfloat16* src = (plane == 0 ? Bhi : Blo)
                                           + (size_t)(col0 + r) * Hh + kk * 32 + c * 8;
                cp16(db + (A_W + plane * PLANE_W) * 4u + swz(r, c), src);
            }
        }
        asm volatile("cp.async.commit_group;" ::: "memory");
    };

    load_stage(0, 0);
    load_stage(1, 1);

    float acc[2][8][4];
    #pragma unroll
    for (int mt = 0; mt < 2; mt++)
        #pragma unroll
        for (int nt = 0; nt < 8; nt++)
            #pragma unroll
            for (int c = 0; c < 4; c++) acc[mt][nt][c] = 0.0f;

    #pragma unroll 1
    for (int kk = 0; kk < 16; kk++) {
        if (kk < 15) asm volatile("cp.async.wait_group 1;" ::: "memory");
        else         asm volatile("cp.async.wait_group 0;" ::: "memory");
        __syncthreads();

        if (kk + 2 < 16) load_stage(kk + 2, (kk + 2) % 3);

        const uint32_t stg  = sbase + (uint32_t)(kk % 3) * (STG_W * 4);
        const uint32_t pA   = stg;
        const uint32_t pBhi = stg + A_W * 4;
        const uint32_t pBlo = stg + (A_W + PLANE_W) * 4;

        #pragma unroll
        for (int ks = 0; ks < 2; ks++) {
            uint32_t ahi[2][4], alo[2][4];
            const uint32_t c0 = 4u * ks + cbase;
            const uint32_t c1 = c0 + 2u;
            #pragma unroll
            for (int mt = 0; mt < 2; mt++) {
                const uint32_t rb = (uint32_t)(wm * 32 + mt * 16);
                const uint32_t r0 = rb + g, r1 = rb + 8 + g;
                const uint32_t x0 = pA + r0 * 128u + ((c0 ^ g) << 4) + wsel;
                const uint32_t x1 = pA + r1 * 128u + ((c0 ^ g) << 4) + wsel;
                const uint32_t x2 = pA + r0 * 128u + ((c1 ^ g) << 4) + wsel;
                const uint32_t x3 = pA + r1 * 128u + ((c1 ^ g) << 4) + wsel;
                cvt_pair(lds64(x0), ahi[mt][0], alo[mt][0]);
                cvt_pair(lds64(x1), ahi[mt][1], alo[mt][1]);
                cvt_pair(lds64(x2), ahi[mt][2], alo[mt][2]);
                cvt_pair(lds64(x3), ahi[mt][3], alo[mt][3]);
            }
            #pragma unroll
            for (int ntp = 0; ntp < 4; ntp++) {
                const uint32_t r = wn * 64 + ntp * 16 + b_row;
                const uint32_t off = swz(r, ks * 2 + b_chk);
                uint32_t bh[4], bl[4];
                ldsm4(bh, pBhi + off);
                ldsm4(bl, pBlo + off);
                #pragma unroll
                for (int half = 0; half < 2; half++) {
                    const int nt = ntp * 2 + half;
                    const uint32_t b0h = bh[half * 2], b1h = bh[half * 2 + 1];
                    const uint32_t b0l = bl[half * 2], b1l = bl[half * 2 + 1];
                    #pragma unroll
                    for (int mt = 0; mt < 2; mt++) {
                        mma_bf16(acc[mt][nt], ahi[mt], b0l, b1l);
                        mma_bf16(acc[mt][nt], alo[mt], b0h, b1h);
                        mma_bf16(acc[mt][nt], ahi[mt], b0h, b1h);
                    }
                }
            }
        }
    }

    #pragma unroll
    for (int mt = 0; mt < 2; mt++) {
        float plo = 0.0f, phi = 0.0f;
        #pragma unroll
        for (int nt = 0; nt < 8; nt++) {
            const int c0 = wn * 64 + nt * 8 + 2 * tg;
            const int c1 = c0 + 1;
            plo += tanh_fast(acc[mt][nt][0] + WRs[c0]) * WVs[c0]
                 + tanh_fast(acc[mt][nt][1] + WRs[c1]) * WVs[c1];
            phi += tanh_fast(acc[mt][nt][2] + WRs[c0]) * WVs[c0]
                 + tanh_fast(acc[mt][nt][3] + WRs[c1]) * WVs[c1];
        }
        plo += __shfl_xor_sync(0xFFFFFFFFu, plo, 1);
        plo += __shfl_xor_sync(0xFFFFFFFFu, plo, 2);
        phi += __shfl_xor_sync(0xFFFFFFFFu, phi, 1);
        phi += __shfl_xor_sync(0xFFFFFFFFu, phi, 2);
        if (tg == 0) {
            sp2[wn * 128 + wm * 32 + mt * 16 + g]     = plo;
            sp2[wn * 128 + wm * 32 + mt * 16 + 8 + g] = phi;
        }
    }
    __syncthreads();
    if (tid < 128)
        scores_part[(size_t)blockIdx.x * (Bsz * Nn) + row0 + tid] =
            sp2[tid] + sp2[128 + tid];
}

// ---------------------------------------------------------------------------
// Per-batch softmax + resp_s (R15 config: grid (512,2), 256 threads)
// ---------------------------------------------------------------------------
__global__ __launch_bounds__(256)
void softmax_weight_kernel(const float* __restrict__ scores_part,
                           const float* __restrict__ mask,
                           const float* __restrict__ emb,
                           float* __restrict__ alpha_out,
                           float* __restrict__ resps)
{
    const int b = blockIdx.x;
    const int half = blockIdx.y;
    const int tid = threadIdx.x;
    __shared__ float sa[256];
    __shared__ float red[256];

    const size_t i = (size_t)b * Nn + tid;
    float s = scores_part[i];
    s += scores_part[(size_t)(Bsz * Nn) + i];
    s += scores_part[(size_t)(2 * Bsz * Nn) + i];
    s += scores_part[(size_t)(3 * Bsz * Nn) + i];
    const float t = s * mask[i];

    red[tid] = t; __syncthreads();
    #pragma unroll
    for (int st = 128; st > 0; st >>= 1) {
        if (tid < st) red[tid] = fmaxf(red[tid], red[tid + st]);
        __syncthreads();
    }
    const float m = red[0];
    __syncthreads();

    const float e = __expf(t - m);
    red[tid] = e; __syncthreads();
    #pragma unroll
    for (int st = 128; st > 0; st >>= 1) {
        if (tid < st) red[tid] += red[tid + st];
        __syncthreads();
    }
    const float a = e / red[0];

    if (half == 0) alpha_out[i] = a;
    sa[tid] = a;
    __syncthreads();

    const int h = half * 256 + tid;
    const float* eb = emb + (size_t)b * Nn * Hh + h;
    float c0 = 0.f, c1 = 0.f, c2 = 0.f, c3 = 0.f;
    float c4 = 0.f, c5 = 0.f, c6 = 0.f, c7 = 0.f;
    #pragma unroll 1
    for (int n = 0; n < Nn; n += 8) {
        c0 = fmaf(sa[n    ], eb[(size_t)(n    ) * Hh], c0);
        c1 = fmaf(sa[n + 1], eb[(size_t)(n + 1) * Hh], c1);
        c2 = fmaf(sa[n + 2], eb[(size_t)(n + 2) * Hh], c2);
        c3 = fmaf(sa[n + 3], eb[(size_t)(n + 3) * Hh], c3);
        c4 = fmaf(sa[n + 4], eb[(size_t)(n + 4) * Hh], c4);
        c5 = fmaf(sa[n + 5], eb[(size_t)(n + 5) * Hh], c5);
        c6 = fmaf(sa[n + 6], eb[(size_t)(n + 6) * Hh], c6);
        c7 = fmaf(sa[n + 7], eb[(size_t)(n + 7) * Hh], c7);
    }
    resps[b * Hh + h] = ((c0 + c1) + (c2 + c3)) + ((c4 + c5) + (c6 + c7));
}

// ---------------------------------------------------------------------------
// Final GEMM split-K8: partial = presps @ Wp^T over 64-wide K chunk
// grid (8 col, 8 row, 8 kc); 64x64 tiles, 4-tile chain.
// ---------------------------------------------------------------------------
__global__ __launch_bounds__(256)
void gemm_final_k(const float* __restrict__ A,
                  const float* __restrict__ B,
                  float* __restrict__ fin_part)
{
    const int kc = blockIdx.z;
    gemm_k<true, 4>(A, B, fin_part + (size_t)kc * HB,
                    blockIdx.y * 64, blockIdx.x * 64, kc * 64);
}

// combine: out = tanh(sum 8 fin partials + sum 4 rx partials)  (deterministic)
__global__ __launch_bounds__(512)
void combine_final(const float* __restrict__ fin_part,
                   const float* __restrict__ dual_part,
                   float* __restrict__ out)
{
    const size_t idx = (size_t)blockIdx.x * 512 + threadIdx.x;
    float f = ((fin_part[idx] + fin_part[HB + idx])
             + (fin_part[2 * (size_t)HB + idx] + fin_part[3 * (size_t)HB + idx]));
    f += ((fin_part[4 * (size_t)HB + idx] + fin_part[5 * (size_t)HB + idx])
        + (fin_part[6 * (size_t)HB + idx] + fin_part[7 * (size_t)HB + idx]));
    const float* rx = dual_part + 4 * (size_t)HB;
    float r = ((rx[idx] + rx[HB + idx])
             + (rx[2 * (size_t)HB + idx] + rx[3 * (size_t)HB + idx]));
    out[idx] = tanhf(f + r);
}

// ---------------------------------------------------------------------------
extern "C" void kernel_launch(void* const* d_in, const int* in_sizes, int n_in,
                              void* d_out, int out_size)
{
    const float* spk  = (const float*)d_in[0];
    const float* mask = (const float*)d_in[1];
    const float* tr   = (const float*)d_in[2];
    const float* Ws   = (const float*)d_in[3];
    const float* Wr   = (const float*)d_in[4];
    const float* w    = (const float*)d_in[5];
    const float* Wp   = (const float*)d_in[6];
    const float* Wx   = (const float*)d_in[7];

    float* out = (float*)d_out;
    float* resp_out  = out;
    float* alpha_out = out + Bsz * Hh;

    float *pspart, *presps, *pdual, *pfin;
    __nv_bfloat16 *pBhi, *pBlo;
    cudaGetSymbolAddress((void**)&pspart, g_scores_part);
    cudaGetSymbolAddress((void**)&presps, g_resps);
    cudaGetSymbolAddress((void**)&pdual, g_dual_part);
    cudaGetSymbolAddress((void**)&pfin, g_fin_part);
    cudaGetSymbolAddress((void**)&pBhi, g_Bhi);
    cudaGetSymbolAddress((void**)&pBlo, g_Blo);

    static bool attr_set = false;
    if (!attr_set) {
        cudaFuncSetAttribute(score_mma,
                             cudaFuncAttributeMaxDynamicSharedMemorySize,
                             SM_BYTES);
        attr_set = true;
    }

    prep_fused<<<640, 256>>>(Ws, tr, Wr, Wx, pBhi, pBlo, pdual);
    score_mma<<<dim3(4, 1024), 256, SM_BYTES>>>(spk, pBhi, pBlo,
                                                pdual, w, pspart);
    softmax_weight_kernel<<<dim3(512, 2), 256>>>(pspart, mask, spk,
                                                 alpha_out, presps);
    gemm_final_k<<<dim3(8, 8, 8), 256>>>(presps, Wp, pfin);
    combine_final<<<512, 512>>>(pfin, pdual, resp_out);
}